// round 15
// baseline (speedup 1.0000x reference)
#include <cuda_runtime.h>
#include <cuda_fp16.h>
#include <cstdint>

#define NTOK   256
#define NPAIRS 512
#define NEXP   8

// ---------------- scratch (device globals) ----------------------------------
__device__ int    g_cnt[NEXP];
__device__ int    g_pairs[NEXP][NPAIRS];
__device__ int    g_pos[NPAIRS];
__device__ __align__(16) __half g_Ah  [NEXP * 512 * 2048];   // gathered x rows, fp16
__device__ __align__(16) __half g_actE[NEXP * 512 * 1024];   // silu(gate)*up, fp16
__device__ float  g_yE  [NEXP * 512 * 2048];                 // GEMM2 out

// ---------------- helpers ----------------------------------------------------
__device__ __forceinline__ uint32_t smem_u32(const void* p) {
    uint32_t a;
    asm("{ .reg .u64 t; cvta.to.shared.u64 t, %1; cvt.u32.u64 %0, t; }" : "=r"(a) : "l"(p));
    return a;
}
__device__ __forceinline__ uint32_t pack_h2(float lo, float hi) {
    uint32_t r;
    asm("cvt.rn.f16x2.f32 %0, %1, %2;" : "=r"(r) : "f"(hi), "f"(lo));
    return r;
}
__device__ __forceinline__ void cpa16(uint32_t dst, const void* src) {
    asm volatile("cp.async.cg.shared.global [%0], [%1], 16;" :: "r"(dst), "l"(src));
}
#define CP_COMMIT() asm volatile("cp.async.commit_group;" ::: "memory")
#define CP_WAIT0()  asm volatile("cp.async.wait_group 0;" ::: "memory")
#define CP_WAIT1()  asm volatile("cp.async.wait_group 1;" ::: "memory")

__device__ __forceinline__ void bar_sync_id(int id) {
    asm volatile("bar.sync %0, 384;" :: "r"(id) : "memory");
}
__device__ __forceinline__ void bar_arrive_id(int id) {
    asm volatile("bar.arrive %0, 384;" :: "r"(id) : "memory");
}

__device__ __forceinline__ void sts128(uint32_t a, uint32_t x, uint32_t y, uint32_t z, uint32_t w) {
    asm volatile("st.shared.v4.b32 [%0], {%1, %2, %3, %4};" :: "r"(a), "r"(x), "r"(y), "r"(z), "r"(w) : "memory");
}
__device__ __forceinline__ void ldsm4(uint32_t& r0, uint32_t& r1, uint32_t& r2, uint32_t& r3, uint32_t a) {
    asm volatile("ldmatrix.sync.aligned.m8n8.x4.shared.b16 {%0,%1,%2,%3}, [%4];"
                 : "=r"(r0), "=r"(r1), "=r"(r2), "=r"(r3) : "r"(a));
}
__device__ __forceinline__ void ldsm2(uint32_t& r0, uint32_t& r1, uint32_t a) {
    asm volatile("ldmatrix.sync.aligned.m8n8.x2.shared.b16 {%0,%1}, [%2];"
                 : "=r"(r0), "=r"(r1) : "r"(a));
}
__device__ __forceinline__ void mma16(float* c, const uint32_t* a, const uint32_t* b) {
    asm volatile("mma.sync.aligned.m16n8k16.row.col.f32.f16.f16.f32 "
                 "{%0,%1,%2,%3}, {%4,%5,%6,%7}, {%8,%9}, {%0,%1,%2,%3};"
                 : "+f"(c[0]), "+f"(c[1]), "+f"(c[2]), "+f"(c[3])
                 : "r"(a[0]), "r"(a[1]), "r"(a[2]), "r"(a[3]), "r"(b[0]), "r"(b[1]));
}

// ---------------- routing ----------------------------------------------------
__global__ void route_kernel(const int* __restrict__ ids) {
    int tid = threadIdx.x;
    if (tid < NEXP) g_cnt[tid] = 0;
    __syncthreads();
    int e   = ids[tid] & 7;
    int pos = atomicAdd(&g_cnt[e], 1);
    g_pairs[e][pos] = tid;
    g_pos[tid] = e * 512 + pos;
}

// ---------------- gather x rows into padded fp16 A (128 rows/expert) ---------
__global__ void gather_kernel(const float* __restrict__ x) {
    int bid = blockIdx.x;               // NEXP*128 blocks: (e, m)
    int e = bid >> 7, m = bid & 127;
    int cnt = g_cnt[e];
    uint4* dst = (uint4*)(g_Ah + ((size_t)e * 512 + m) * 2048);
    int tid = threadIdx.x;
    if (m < cnt) {
        int p = g_pairs[e][m];
        const float4* src = (const float4*)(x + (size_t)(p >> 1) * 2048) + tid * 2;
        float4 v0 = src[0], v1 = src[1];
        uint4 o;
        o.x = pack_h2(v0.x, v0.y); o.y = pack_h2(v0.z, v0.w);
        o.z = pack_h2(v1.x, v1.y); o.w = pack_h2(v1.z, v1.w);
        dst[tid] = o;
    } else {
        dst[tid] = make_uint4(0, 0, 0, 0);
    }
}

// ---------------- warp-specialized fp16 mma GEMM, BM=64, 2 CTAs/SM ------------
// 384 threads: warps 0-7 consumers (2m x 4n, warp tile 32x32), warps 8-11
// producers with R12's proven single-batch staging (LDG full stage before the
// EMPTY wait). Producer addressing uses 2 base pointers + compile-time row
// offsets (i*16*KTOT) so regs fit the 84-reg cap of __launch_bounds__(384,2).
// BM=64, BN=128, BK=64. Ring: 3 x { B 128x144B, A 64x144B } = 82944 B.
// FULL_b = bar 1+b, EMPTY_b = bar 4+b (count 384).
#define STGB 18432u                     // B stage: 128 rows * 144B
#define ASTG 9216u                      // A stage: 64 rows * 144B
#define SMEM_DYN (3 * 18432 + 3 * 9216) // 82944 -> 2 CTAs/SM

template<int KTOT, bool G1>
__global__ void __launch_bounds__(384, 2) mma_gemm(
    const float* __restrict__ Ball,
    const float* __restrict__ Sall)
{
    constexpr int KS = KTOT / 64;
    constexpr int KB = KTOT / 128;

    const int e   = blockIdx.z;
    const int cnt = g_cnt[e];
    const int m0  = (int)blockIdx.y << 6;
    if (m0 >= cnt) return;              // uniform per CTA
    const int n0  = G1 ? ((int)blockIdx.x << 6) : ((int)blockIdx.x << 7);

    const __half* Ah = (G1 ? g_Ah : g_actE) + ((size_t)e * 512 + m0) * KTOT;

    extern __shared__ float dsm[];
    const uint32_t sb  = smem_u32(dsm);
    const uint32_t aA0 = sb + 3 * STGB;

    const int tid  = threadIdx.x;
    const int lane = tid & 31, w = tid >> 5;
    const int warpM = (w & 1) << 5;     // 0 or 32 (consumers)
    const int warpN = (w >> 1) << 5;    // 0,32,64,96 (consumers)

    float acc[2][4][4] = {};

    if (w >= 8) {
        // ================= producer: R12-style single-batch staging =========
        const int tp = tid - 256;       // 0..127
        const int rg = tp >> 3, c16 = tp & 7;
        // rows rg+16i: i<4 from base1 (gate / first 64), i>=4 from base2
        const float* B1 = Ball + ((size_t)e * 2048 + n0 + rg) * KTOT + c16 * 8;
        const float* B2 = G1
            ? (Ball + ((size_t)e * 2048 + 1024 + n0 + rg) * KTOT + c16 * 8)
            : (B1 + (size_t)64 * KTOT);
        const float* S1 = Sall + ((size_t)e * 16 + (n0 >> 7)) * KB;
        const float* S2 = G1 ? (S1 + 8 * KB) : S1;

        float4 u[8], v[8];
        // prologue: LDG stage 0
#pragma unroll
        for (int i = 0; i < 8; i++) {
            const float* p = (i < 4) ? (B1 + (size_t)i * 16 * KTOT)
                                     : (B2 + (size_t)(i - 4) * 16 * KTOT);
            u[i] = *(const float4*)(p);
            v[i] = *(const float4*)(p + 4);
        }
        for (int s = 0; s < KS; s++) {
            const int b = s % 3;
            bar_sync_id(4 + b);                 // buffer b free (LDGs already in flight)
            const uint32_t bB = sb + (uint32_t)b * STGB;
            const float s1 = S1[s >> 1], s2 = S2[s >> 1];
#pragma unroll
            for (int i = 0; i < 8; i++) {
                const float sc = (i < 4) ? s1 : s2;
                sts128(bB + (uint32_t)((rg + 16 * i) * 144 + c16 * 16),
                       pack_h2(u[i].x * sc, u[i].y * sc),
                       pack_h2(u[i].z * sc, u[i].w * sc),
                       pack_h2(v[i].x * sc, v[i].y * sc),
                       pack_h2(v[i].z * sc, v[i].w * sc));
            }
            bar_arrive_id(1 + b);               // buffer b full
            if (s + 1 < KS) {                   // LDG stage s+1 (lands during next EMPTY wait)
                const int kf = (s + 1) * 64;
#pragma unroll
                for (int i = 0; i < 8; i++) {
                    const float* p = ((i < 4) ? (B1 + (size_t)i * 16 * KTOT)
                                              : (B2 + (size_t)(i - 4) * 16 * KTOT)) + kf;
                    u[i] = *(const float4*)(p);
                    v[i] = *(const float4*)(p + 4);
                }
            }
        }
    } else {
        // ================= consumer: A cp.async + MMA =================
        const int l2 = lane & 15;
        const uint32_t aFB = (uint32_t)((warpM + (lane & 7) + ((lane >> 3) & 1) * 8) * 144
                                        + (lane >> 4) * 16);
        const uint32_t bFB = (uint32_t)((warpN + (l2 & 7)) * 144 + ((l2 >> 3) & 1) * 16);
        const int ar = tid >> 3, ac = tid & 7;  // A rows ar+32j, j<2

        bar_arrive_id(4); bar_arrive_id(5); bar_arrive_id(6);   // bufs start empty

        // prologue: A stages 0,1 in flight
#pragma unroll
        for (int ps = 0; ps < 2; ps++) {
            const uint32_t dA = aA0 + (uint32_t)ps * ASTG;
#pragma unroll
            for (int j = 0; j < 2; j++)
                cpa16(dA + (uint32_t)((ar + 32 * j) * 144 + ac * 16),
                      Ah + (size_t)(ar + 32 * j) * KTOT + ps * 64 + ac * 8);
            CP_COMMIT();
        }

        for (int s = 0; s < KS; s++) {
            const int b = s % 3;
            if (s + 1 < KS) CP_WAIT1(); else CP_WAIT0();   // A stage s landed
            bar_sync_id(1 + b);                            // B stage s ready
            if (s + 2 < KS) {
                const uint32_t dA = aA0 + (uint32_t)((s + 2) % 3) * ASTG;
#pragma unroll
                for (int j = 0; j < 2; j++)
                    cpa16(dA + (uint32_t)((ar + 32 * j) * 144 + ac * 16),
                          Ah + (size_t)(ar + 32 * j) * KTOT + (s + 2) * 64 + ac * 8);
                CP_COMMIT();
            }
            const uint32_t bS = sb  + (uint32_t)b * STGB;
            const uint32_t aS = aA0 + (uint32_t)b * ASTG;
#pragma unroll
            for (int ss = 0; ss < 4; ss++) {
                uint32_t af[2][4], bf[4][2];
#pragma unroll
                for (int mt = 0; mt < 2; mt++)
                    ldsm4(af[mt][0], af[mt][1], af[mt][2], af[mt][3],
                          aS + aFB + (uint32_t)(mt * 16 * 144 + ss * 32));
#pragma unroll
                for (int nt = 0; nt < 4; nt++)
                    ldsm2(bf[nt][0], bf[nt][1],
                          bS + bFB + (uint32_t)(nt * 8 * 144 + ss * 32));
#pragma unroll
                for (int mt = 0; mt < 2; mt++)
#pragma unroll
                    for (int nt = 0; nt < 4; nt++)
                        mma16(acc[mt][nt], af[mt], bf[nt]);
            }
            bar_arrive_id(4 + b);                          // buffer b free
        }
    }

    // ================= epilogue =================
    const int rr = lane >> 2, cc = (lane & 3) << 1;
    if (!G1) {
        if (w < 8) {
            float* Cb = g_yE + ((size_t)e * 512 + m0) * 2048 + n0;
#pragma unroll
            for (int mt = 0; mt < 2; mt++)
#pragma unroll
                for (int nt = 0; nt < 4; nt++) {
                    float* p0 = Cb + (size_t)(warpM + mt * 16 + rr) * 2048 + warpN + nt * 8 + cc;
                    *(float2*)p0 = make_float2(acc[mt][nt][0], acc[mt][nt][1]);
                    *(float2*)(p0 + 8 * 2048) = make_float2(acc[mt][nt][2], acc[mt][nt][3]);
                }
        }
    } else {
        // fused silu(gate)*up: up warps (warpN>=64) stage accs via smem
        __syncthreads();
        float* ups = dsm;               // 64 rows x 68 floats (17.4KB, reuses ring)
        if (w < 8 && warpN >= 64) {
            const int wn = warpN - 64;
#pragma unroll
            for (int mt = 0; mt < 2; mt++)
#pragma unroll
                for (int nt = 0; nt < 4; nt++) {
                    int row = warpM + mt * 16 + rr;
                    int col = wn + nt * 8 + cc;
                    *(float2*)(ups + row * 68 + col)       = make_float2(acc[mt][nt][0], acc[mt][nt][1]);
                    *(float2*)(ups + (row + 8) * 68 + col) = make_float2(acc[mt][nt][2], acc[mt][nt][3]);
                }
        }
        __syncthreads();
        if (w < 8 && warpN < 64) {
            __half* act = g_actE + ((size_t)e * 512 + m0) * 1024 + n0;
#pragma unroll
            for (int mt = 0; mt < 2; mt++)
#pragma unroll
                for (int nt = 0; nt < 4; nt++) {
                    int row = warpM + mt * 16 + rr;
                    int col = warpN + nt * 8 + cc;
                    float2 u0 = *(float2*)(ups + row * 68 + col);
                    float2 u1 = *(float2*)(ups + (row + 8) * 68 + col);
                    float g0 = acc[mt][nt][0], g1 = acc[mt][nt][1];
                    float g2 = acc[mt][nt][2], g3 = acc[mt][nt][3];
                    float a0 = g0 / (1.f + __expf(-g0)) * u0.x;
                    float a1 = g1 / (1.f + __expf(-g1)) * u0.y;
                    float a2 = g2 / (1.f + __expf(-g2)) * u1.x;
                    float a3 = g3 / (1.f + __expf(-g3)) * u1.y;
                    *(uint32_t*)(act + (size_t)row * 1024 + col)       = pack_h2(a0, a1);
                    *(uint32_t*)(act + (size_t)(row + 8) * 1024 + col) = pack_h2(a2, a3);
                }
        }
    }
}

// ---------------- combine -------------------------------------------------------
__global__ void combine_kernel(const float* __restrict__ tw,
                               float* __restrict__ out) {
    int idx = blockIdx.x * 256 + threadIdx.x;     // over 256*2048/4
    int t  = idx >> 9;
    int h4 = (idx & 511) << 2;
    float w0 = tw[2 * t + 0], w1 = tw[2 * t + 1];
    const float4* y0 = (const float4*)(g_yE + (size_t)g_pos[2 * t + 0] * 2048 + h4);
    const float4* y1 = (const float4*)(g_yE + (size_t)g_pos[2 * t + 1] * 2048 + h4);
    float4 a = *y0, b = *y1;
    *(float4*)(out + (size_t)t * 2048 + h4) = make_float4(
        w0 * a.x + w1 * b.x, w0 * a.y + w1 * b.y,
        w0 * a.z + w1 * b.z, w0 * a.w + w1 * b.w);
}

// ---------------- entry ---------------------------------------------------------
extern "C" void kernel_launch(void* const* d_in, const int* in_sizes, int n_in,
                              void* d_out, int out_size) {
    const float* x   = (const float*)d_in[0];
    const int*   ids = (const int*)d_in[1];
    const float* tw  = (const float*)d_in[2];
    const float* w13 = (const float*)d_in[3];
    const float* s13 = (const float*)d_in[4];
    const float* w2  = (const float*)d_in[5];
    const float* s2  = (const float*)d_in[6];
    float* out = (float*)d_out;

    cudaFuncSetAttribute(mma_gemm<2048, true>,  cudaFuncAttributeMaxDynamicSharedMemorySize, SMEM_DYN);
    cudaFuncSetAttribute(mma_gemm<1024, false>, cudaFuncAttributeMaxDynamicSharedMemorySize, SMEM_DYN);

    route_kernel<<<1, NPAIRS>>>(ids);
    gather_kernel<<<NEXP * 128, 256>>>(x);

    dim3 grid(16, 2, NEXP);             // n-tiles x m-tiles(64) x experts
    mma_gemm<2048, true><<<grid, 384, SMEM_DYN>>>(w13, s13);   // gate_up + silu fused
    mma_gemm<1024, false><<<grid, 384, SMEM_DYN>>>(w2, s2);    // down proj

    combine_kernel<<<(NTOK * 2048 / 4) / 256, 256>>>(tw, out);
}

// round 16
// speedup vs baseline: 1.6965x; 1.6965x over previous
#include <cuda_runtime.h>
#include <cuda_fp16.h>
#include <cstdint>

#define NTOK   256
#define NPAIRS 512
#define NEXP   8

// ---------------- scratch (device globals) ----------------------------------
__device__ int    g_cnt[NEXP];
__device__ int    g_pairs[NEXP][NPAIRS];
__device__ int    g_pos[NPAIRS];
__device__ __align__(16) __half g_Ah  [NEXP * 512 * 2048];   // gathered x rows, fp16
__device__ __align__(16) __half g_actE[NEXP * 512 * 1024];   // silu(gate)*up, fp16
__device__ float  g_yE  [NEXP * 512 * 2048];                 // GEMM2 out

// ---------------- helpers ----------------------------------------------------
__device__ __forceinline__ uint32_t smem_u32(const void* p) {
    uint32_t a;
    asm("{ .reg .u64 t; cvta.to.shared.u64 t, %1; cvt.u32.u64 %0, t; }" : "=r"(a) : "l"(p));
    return a;
}
__device__ __forceinline__ uint32_t pack_h2(float lo, float hi) {
    uint32_t r;
    asm("cvt.rn.f16x2.f32 %0, %1, %2;" : "=r"(r) : "f"(hi), "f"(lo));
    return r;
}
__device__ __forceinline__ void cpa16(uint32_t dst, const void* src) {
    asm volatile("cp.async.cg.shared.global [%0], [%1], 16;" :: "r"(dst), "l"(src));
}
#define CP_COMMIT() asm volatile("cp.async.commit_group;" ::: "memory")
#define CP_WAIT0()  asm volatile("cp.async.wait_group 0;" ::: "memory")
#define CP_WAIT1()  asm volatile("cp.async.wait_group 1;" ::: "memory")

__device__ __forceinline__ void bar_sync_id(int id) {
    asm volatile("bar.sync %0, 384;" :: "r"(id) : "memory");
}
__device__ __forceinline__ void bar_arrive_id(int id) {
    asm volatile("bar.arrive %0, 384;" :: "r"(id) : "memory");
}

__device__ __forceinline__ void sts128(uint32_t a, uint32_t x, uint32_t y, uint32_t z, uint32_t w) {
    asm volatile("st.shared.v4.b32 [%0], {%1, %2, %3, %4};" :: "r"(a), "r"(x), "r"(y), "r"(z), "r"(w) : "memory");
}
__device__ __forceinline__ void ldsm4(uint32_t& r0, uint32_t& r1, uint32_t& r2, uint32_t& r3, uint32_t a) {
    asm volatile("ldmatrix.sync.aligned.m8n8.x4.shared.b16 {%0,%1,%2,%3}, [%4];"
                 : "=r"(r0), "=r"(r1), "=r"(r2), "=r"(r3) : "r"(a));
}
__device__ __forceinline__ void ldsm2(uint32_t& r0, uint32_t& r1, uint32_t a) {
    asm volatile("ldmatrix.sync.aligned.m8n8.x2.shared.b16 {%0,%1}, [%2];"
                 : "=r"(r0), "=r"(r1) : "r"(a));
}
__device__ __forceinline__ void mma16(float* c, const uint32_t* a, const uint32_t* b) {
    asm volatile("mma.sync.aligned.m16n8k16.row.col.f32.f16.f16.f32 "
                 "{%0,%1,%2,%3}, {%4,%5,%6,%7}, {%8,%9}, {%0,%1,%2,%3};"
                 : "+f"(c[0]), "+f"(c[1]), "+f"(c[2]), "+f"(c[3])
                 : "r"(a[0]), "r"(a[1]), "r"(a[2]), "r"(a[3]), "r"(b[0]), "r"(b[1]));
}

// ---------------- routing ----------------------------------------------------
__global__ void route_kernel(const int* __restrict__ ids) {
    int tid = threadIdx.x;
    if (tid < NEXP) g_cnt[tid] = 0;
    __syncthreads();
    int e   = ids[tid] & 7;
    int pos = atomicAdd(&g_cnt[e], 1);
    g_pairs[e][pos] = tid;
    g_pos[tid] = e * 512 + pos;
}

// ---------------- gather x rows into padded fp16 A (128 rows/expert) ---------
__global__ void gather_kernel(const float* __restrict__ x) {
    int bid = blockIdx.x;               // NEXP*128 blocks: (e, m)
    int e = bid >> 7, m = bid & 127;
    int cnt = g_cnt[e];
    uint4* dst = (uint4*)(g_Ah + ((size_t)e * 512 + m) * 2048);
    int tid = threadIdx.x;
    if (m < cnt) {
        int p = g_pairs[e][m];
        const float4* src = (const float4*)(x + (size_t)(p >> 1) * 2048) + tid * 2;
        float4 v0 = src[0], v1 = src[1];
        uint4 o;
        o.x = pack_h2(v0.x, v0.y); o.y = pack_h2(v0.z, v0.w);
        o.z = pack_h2(v1.x, v1.y); o.w = pack_h2(v1.z, v1.w);
        dst[tid] = o;
    } else {
        dst[tid] = make_uint4(0, 0, 0, 0);
    }
}

// ---------------- warp-specialized GEMM: dual producer groups -----------------
// 512 threads: warps 0-7 consumers (R12 layout: 2m x 4n, warp tile 64x32),
// warps 8-11 = producer group 0 (even stages), warps 12-15 = group 1 (odd).
// Each group stages ONE 64-reg LDG batch per own stage, but the two groups
// overlap -> two weight stages continuously in flight (Little's law: ~2x BW).
// BM=128, BN=128, BK=64. Ring: 4 x { B fp16 128x144B } + 4 x { A 128x144B }.
// FULL_b = bar 1+b, EMPTY_b = bar 5+b; count 384 = 256 consumers + owner group.
#define STGB 18432u                     // 128 rows * 144B
#define SMEM_DYN (8 * 18432)            // 147456 B, 1 CTA/SM

template<int KTOT, bool G1>
__global__ void __launch_bounds__(512, 1) mma_gemm(
    const float* __restrict__ Ball,
    const float* __restrict__ Sall)
{
    constexpr int KS = KTOT / 64;
    constexpr int KB = KTOT / 128;

    const int e   = blockIdx.z;
    const int cnt = g_cnt[e];
    if (cnt == 0) return;               // uniform per CTA
    const int n0  = G1 ? ((int)blockIdx.x << 6) : ((int)blockIdx.x << 7);

    const __half* Ah = (G1 ? g_Ah : g_actE) + (size_t)e * 512 * KTOT;

    extern __shared__ float dsm[];
    const uint32_t sb  = smem_u32(dsm);
    const uint32_t aA0 = sb + 4 * STGB;

    const int tid  = threadIdx.x;
    const int lane = tid & 31, w = tid >> 5;
    const int warpM = (w & 1) << 6;     // 0 or 64 (consumers)
    const int warpN = (w >> 1) << 5;    // 0,32,64,96 (consumer warps 0-7)

    float acc[4][4][4] = {};            // consumer accumulators

    if (w >= 8) {
        // ========== producer group g: stages s = g, g+2, g+4, ... ==========
        const int g  = (w >= 12) ? 1 : 0;
        const int tp = tid - 256 - g * 128;   // 0..127
        const int rg = tp >> 3, c16 = tp & 7;
        // rows rg+16i: i<4 from base1 (gate / first 64), i>=4 from base2
        const float* B1 = Ball + ((size_t)e * 2048 + n0 + rg) * KTOT + c16 * 8;
        const float* B2 = G1
            ? (Ball + ((size_t)e * 2048 + 1024 + n0 + rg) * KTOT + c16 * 8)
            : (B1 + (size_t)64 * KTOT);
        const float* S1 = Sall + ((size_t)e * 16 + (n0 >> 7)) * KB;
        const float* S2 = G1 ? (S1 + 8 * KB) : S1;

        float4 u[8], v[8];
        // prologue: LDG own first stage (s = g)
        {
            const int kf = g * 64;
#pragma unroll
            for (int i = 0; i < 8; i++) {
                const float* p = ((i < 4) ? (B1 + (size_t)i * 16 * KTOT)
                                          : (B2 + (size_t)(i - 4) * 16 * KTOT)) + kf;
                u[i] = *(const float4*)(p);
                v[i] = *(const float4*)(p + 4);
            }
        }
        for (int s = g; s < KS; s += 2) {
            const int b = s & 3;
            bar_sync_id(5 + b);                 // buffer b free (LDGs in flight)
            const uint32_t bB = sb + (uint32_t)b * STGB;
            const float s1 = S1[s >> 1], s2 = S2[s >> 1];
#pragma unroll
            for (int i = 0; i < 8; i++) {
                const float sc = (i < 4) ? s1 : s2;
                sts128(bB + (uint32_t)((rg + 16 * i) * 144 + c16 * 16),
                       pack_h2(u[i].x * sc, u[i].y * sc),
                       pack_h2(u[i].z * sc, u[i].w * sc),
                       pack_h2(v[i].x * sc, v[i].y * sc),
                       pack_h2(v[i].z * sc, v[i].w * sc));
            }
            bar_arrive_id(1 + b);               // buffer b full
            if (s + 2 < KS) {                   // LDG own next stage; ~2 consumer
                const int kf = (s + 2) * 64;    // periods to land
#pragma unroll
                for (int i = 0; i < 8; i++) {
                    const float* p = ((i < 4) ? (B1 + (size_t)i * 16 * KTOT)
                                              : (B2 + (size_t)(i - 4) * 16 * KTOT)) + kf;
                    u[i] = *(const float4*)(p);
                    v[i] = *(const float4*)(p + 4);
                }
            }
        }
    } else {
        // ================= consumer: A cp.async + MMA (R12 layout) ==========
        const int l2 = lane & 15;
        const uint32_t aFB = (uint32_t)((warpM + (lane & 7) + ((lane >> 3) & 1) * 8) * 144
                                        + (lane >> 4) * 16);
        const uint32_t bFB = (uint32_t)((warpN + (l2 & 7)) * 144 + ((l2 >> 3) & 1) * 16);
        const int ar = tid >> 3, ac = tid & 7;  // A granules: rows ar+32j, j<4

        bar_arrive_id(5); bar_arrive_id(6); bar_arrive_id(7); bar_arrive_id(8);

        // prologue: A stages 0,1 in flight
#pragma unroll
        for (int ps = 0; ps < 2; ps++) {
            const uint32_t dA = aA0 + (uint32_t)ps * STGB;
#pragma unroll
            for (int j = 0; j < 4; j++)
                cpa16(dA + (uint32_t)((ar + 32 * j) * 144 + ac * 16),
                      Ah + (size_t)(ar + 32 * j) * KTOT + ps * 64 + ac * 8);
            CP_COMMIT();
        }

        for (int s = 0; s < KS; s++) {
            const int b = s & 3;
            if (s + 1 < KS) CP_WAIT1(); else CP_WAIT0();  // A stage s landed
            bar_sync_id(1 + b);                           // B stage s ready
            if (s + 2 < KS) {                             // A stage s+2
                const uint32_t dA = aA0 + (uint32_t)((s + 2) & 3) * STGB;
#pragma unroll
                for (int j = 0; j < 4; j++)
                    cpa16(dA + (uint32_t)((ar + 32 * j) * 144 + ac * 16),
                          Ah + (size_t)(ar + 32 * j) * KTOT + (s + 2) * 64 + ac * 8);
                CP_COMMIT();
            }
            const uint32_t bS = sb  + (uint32_t)b * STGB;
            const uint32_t aS = aA0 + (uint32_t)b * STGB;
#pragma unroll
            for (int ss = 0; ss < 4; ss++) {
                uint32_t af[4][4], bf[4][2];
#pragma unroll
                for (int mt = 0; mt < 4; mt++)
                    ldsm4(af[mt][0], af[mt][1], af[mt][2], af[mt][3],
                          aS + aFB + (uint32_t)(mt * 16 * 144 + ss * 32));
#pragma unroll
                for (int nt = 0; nt < 4; nt++)
                    ldsm2(bf[nt][0], bf[nt][1],
                          bS + bFB + (uint32_t)(nt * 8 * 144 + ss * 32));
#pragma unroll
                for (int mt = 0; mt < 4; mt++)
#pragma unroll
                    for (int nt = 0; nt < 4; nt++)
                        mma16(acc[mt][nt], af[mt], bf[nt]);
            }
            bar_arrive_id(5 + b);                         // buffer b free
        }
    }

    // ================= epilogue =================
    const int rr = lane >> 2, cc = (lane & 3) << 1;
    if (!G1) {
        if (w < 8) {
            float* Cb = g_yE + (size_t)e * 512 * 2048 + n0;
#pragma unroll
            for (int mt = 0; mt < 4; mt++)
#pragma unroll
                for (int nt = 0; nt < 4; nt++) {
                    float* p0 = Cb + (size_t)(warpM + mt * 16 + rr) * 2048 + warpN + nt * 8 + cc;
                    *(float2*)p0 = make_float2(acc[mt][nt][0], acc[mt][nt][1]);
                    *(float2*)(p0 + 8 * 2048) = make_float2(acc[mt][nt][2], acc[mt][nt][3]);
                }
        }
    } else {
        // fused silu(gate)*up: up warps (warpN>=64) stage accs via smem
        __syncthreads();
        float* ups = dsm;               // 128 rows x 68 floats (34.8KB, reuses ring)
        if (w < 8 && warpN >= 64) {
            const int wn = warpN - 64;
#pragma unroll
            for (int mt = 0; mt < 4; mt++)
#pragma unroll
                for (int nt = 0; nt < 4; nt++) {
                    int row = warpM + mt * 16 + rr;
                    int col = wn + nt * 8 + cc;
                    *(float2*)(ups + row * 68 + col)       = make_float2(acc[mt][nt][0], acc[mt][nt][1]);
                    *(float2*)(ups + (row + 8) * 68 + col) = make_float2(acc[mt][nt][2], acc[mt][nt][3]);
                }
        }
        __syncthreads();
        if (w < 8 && warpN < 64) {
            __half* act = g_actE + (size_t)e * 512 * 1024 + n0;
#pragma unroll
            for (int mt = 0; mt < 4; mt++)
#pragma unroll
                for (int nt = 0; nt < 4; nt++) {
                    int row = warpM + mt * 16 + rr;
                    int col = warpN + nt * 8 + cc;
                    float2 u0 = *(float2*)(ups + row * 68 + col);
                    float2 u1 = *(float2*)(ups + (row + 8) * 68 + col);
                    float g0 = acc[mt][nt][0], g1 = acc[mt][nt][1];
                    float g2 = acc[mt][nt][2], g3 = acc[mt][nt][3];
                    float a0 = g0 / (1.f + __expf(-g0)) * u0.x;
                    float a1 = g1 / (1.f + __expf(-g1)) * u0.y;
                    float a2 = g2 / (1.f + __expf(-g2)) * u1.x;
                    float a3 = g3 / (1.f + __expf(-g3)) * u1.y;
                    *(uint32_t*)(act + (size_t)row * 1024 + col)       = pack_h2(a0, a1);
                    *(uint32_t*)(act + (size_t)(row + 8) * 1024 + col) = pack_h2(a2, a3);
                }
        }
    }
}

// ---------------- combine -------------------------------------------------------
__global__ void combine_kernel(const float* __restrict__ tw,
                               float* __restrict__ out) {
    int idx = blockIdx.x * 256 + threadIdx.x;     // over 256*2048/4
    int t  = idx >> 9;
    int h4 = (idx & 511) << 2;
    float w0 = tw[2 * t + 0], w1 = tw[2 * t + 1];
    const float4* y0 = (const float4*)(g_yE + (size_t)g_pos[2 * t + 0] * 2048 + h4);
    const float4* y1 = (const float4*)(g_yE + (size_t)g_pos[2 * t + 1] * 2048 + h4);
    float4 a = *y0, b = *y1;
    *(float4*)(out + (size_t)t * 2048 + h4) = make_float4(
        w0 * a.x + w1 * b.x, w0 * a.y + w1 * b.y,
        w0 * a.z + w1 * b.z, w0 * a.w + w1 * b.w);
}

// ---------------- entry ---------------------------------------------------------
extern "C" void kernel_launch(void* const* d_in, const int* in_sizes, int n_in,
                              void* d_out, int out_size) {
    const float* x   = (const float*)d_in[0];
    const int*   ids = (const int*)d_in[1];
    const float* tw  = (const float*)d_in[2];
    const float* w13 = (const float*)d_in[3];
    const float* s13 = (const float*)d_in[4];
    const float* w2  = (const float*)d_in[5];
    const float* s2  = (const float*)d_in[6];
    float* out = (float*)d_out;

    cudaFuncSetAttribute(mma_gemm<2048, true>,  cudaFuncAttributeMaxDynamicSharedMemorySize, SMEM_DYN);
    cudaFuncSetAttribute(mma_gemm<1024, false>, cudaFuncAttributeMaxDynamicSharedMemorySize, SMEM_DYN);

    route_kernel<<<1, NPAIRS>>>(ids);
    gather_kernel<<<NEXP * 128, 256>>>(x);

    dim3 grid(16, 1, NEXP);             // 128 CTAs = one wave on 148 SMs
    mma_gemm<2048, true><<<grid, 512, SMEM_DYN>>>(w13, s13);   // gate_up + silu fused
    mma_gemm<1024, false><<<grid, 512, SMEM_DYN>>>(w2, s2);    // down proj

    combine_kernel<<<(NTOK * 2048 / 4) / 256, 256>>>(tw, out);
}